// round 9
// baseline (speedup 1.0000x reference)
#include <cuda_runtime.h>
#include <cuda_fp16.h>
#include <cuda_bf16.h>
#include <stdint.h>
#include <math.h>

#define N_ATOMS 100000
#define M_NBR   12
#define F_DIM   64
#define C_DIM   128
#define KW      192
#define P_ROWS  (N_ATOMS * M_NBR)  // 1200000
#define BN_EPS  1e-5f
#define NWTILES (P_ROWS / 32)      // 37500 warp-tiles of 32 rows

typedef unsigned long long u64;

// ---------------- scratch ----------------
__device__ __align__(256) float  g_S [N_ATOMS * C_DIM];
__device__ __align__(256) float  g_P [N_ATOMS * C_DIM];
__device__ __align__(256) __half g_Zh[(size_t)P_ROWS * C_DIM];
__device__ __align__(256) float  g_NS[N_ATOMS * F_DIM];
__device__ __align__(256) __nv_bfloat16 g_Wh[C_DIM * 64];   // W_edge hi (bf16)
__device__ __align__(256) __nv_bfloat16 g_Wl[C_DIM * 64];   // W_edge lo (bf16)
__device__ float g_stats1[2 * C_DIM];
__device__ float g_stats2[2 * F_DIM];
__device__ float g_aff1 [2 * C_DIM];
__device__ float g_aff2 [2 * F_DIM];

// ---------------- helpers ----------------
__device__ __forceinline__ u64 pack2(float lo, float hi) {
    u64 r; asm("mov.b64 %0, {%1, %2};" : "=l"(r) : "r"(__float_as_uint(lo)), "r"(__float_as_uint(hi))); return r;
}
__device__ __forceinline__ u64 dup2(float a) {
    u64 r; unsigned int u = __float_as_uint(a);
    asm("mov.b64 %0, {%1, %1};" : "=l"(r) : "r"(u)); return r;
}
__device__ __forceinline__ u64 ffma2(u64 a, u64 b, u64 c) {
    u64 d; asm("fma.rn.f32x2 %0, %1, %2, %3;" : "=l"(d) : "l"(a), "l"(b), "l"(c)); return d;
}
__device__ __forceinline__ float tanh_fast(float x) {
    float y; asm("tanh.approx.f32 %0, %1;" : "=f"(y) : "f"(x)); return y;
}
__device__ __forceinline__ float sigmoid_fast(float x) {
    return fmaf(0.5f, tanh_fast(0.5f * x), 0.5f);
}
__device__ __forceinline__ float softplus_fast(float x) {
    return fmaxf(x, 0.f) + __logf(1.f + __expf(-fabsf(x)));
}
__device__ __forceinline__ uint32_t smem_u32(const void* p) {
    uint32_t a;
    asm("{ .reg .u64 t; cvta.to.shared.u64 t, %1; cvt.u32.u64 %0, t; }" : "=r"(a) : "l"(p));
    return a;
}
#define SWZ(b) ((b) ^ (((b) >> 3) & 0x70))

__device__ __forceinline__ void ldsm4(uint32_t* r, uint32_t addr) {
    asm volatile("ldmatrix.sync.aligned.m8n8.x4.shared.b16 {%0,%1,%2,%3}, [%4];"
        : "=r"(r[0]), "=r"(r[1]), "=r"(r[2]), "=r"(r[3]) : "r"(addr));
}
__device__ __forceinline__ void mma_bf16(float* d, const uint32_t* a, const uint32_t* b) {
    asm volatile("mma.sync.aligned.m16n8k16.row.col.f32.bf16.bf16.f32 "
        "{%0,%1,%2,%3}, {%4,%5,%6,%7}, {%8,%9}, {%0,%1,%2,%3};"
        : "+f"(d[0]), "+f"(d[1]), "+f"(d[2]), "+f"(d[3])
        : "r"(a[0]), "r"(a[1]), "r"(a[2]), "r"(a[3]), "r"(b[0]), "r"(b[1]));
}

// k2 smem layout (dynamic, 96KB)
#define SM_B_HI 0
#define SM_B_LO 16384
#define SM_A_HI 32768       // + wid*4096 per-warp slice (32 rows x 128B)
#define SM_A_LO 49152
#define SM_E    65536       // + wid*8192 per-warp f32 stage (32 x 64)
#define SM_TOT  98304

// ---------------- K0: zero stats + split W_edge to bf16 hi/lo --------------
__global__ void k0_zero(const float* __restrict__ W) {
    int t = blockIdx.x * blockDim.x + threadIdx.x;
    if (t < 2 * C_DIM) g_stats1[t] = 0.f;
    if (t < 2 * F_DIM) g_stats2[t] = 0.f;
    for (int i = t; i < C_DIM * 64; i += gridDim.x * blockDim.x) {
        int c = i >> 6, k = i & 63;
        float x = W[c * KW + 128 + k];
        __nv_bfloat16 hi = __float2bfloat16(x);
        __nv_bfloat16 lo = __float2bfloat16(x - __bfloat162float(hi));
        g_Wh[i] = hi; g_Wl[i] = lo;
    }
}

__global__ void knop() {}

// ---------------- K1: S, P precompute (FFMA2 path) ----------------
__global__ __launch_bounds__(128, 4) void k1_selfnbr(
        const float* __restrict__ atom, const float* __restrict__ W,
        const float* __restrict__ b) {
    __shared__ __align__(16) float sW[64 * 128];
    __shared__ __align__(16) float sA[64 * 36];
    const int tid = threadIdx.x;
    const int n0  = blockIdx.x * 32;
    for (int i = tid; i < 32 * 64; i += 128) {
        int r = i >> 6, k = i & 63;
        sA[k * 36 + r] = atom[(n0 + r) * 64 + k];
    }
    const int rg = tid >> 4, cg = tid & 15;
    const int r0 = rg * 4,  c0 = cg * 8;
    for (int half = 0; half < 2; ++half) {
        __syncthreads();
        for (int i = tid; i < 64 * 128; i += 128) {
            int c = i >> 6, k = i & 63;
            sW[k * 128 + c] = W[c * KW + half * 64 + k];
        }
        __syncthreads();
        u64 acc[4][4];
        #pragma unroll
        for (int r = 0; r < 4; r++)
            #pragma unroll
            for (int cp = 0; cp < 4; cp++)
                acc[r][cp] = (half == 0) ? pack2(b[c0 + 2*cp], b[c0 + 2*cp + 1]) : 0ULL;
        #pragma unroll 8
        for (int k = 0; k < 64; ++k) {
            float4 av = *(const float4*)&sA[k * 36 + r0];
            ulonglong2 w0 = *(const ulonglong2*)&sW[k * 128 + c0];
            ulonglong2 w1 = *(const ulonglong2*)&sW[k * 128 + c0 + 4];
            u64 ad[4] = {dup2(av.x), dup2(av.y), dup2(av.z), dup2(av.w)};
            u64 wp[4] = {w0.x, w0.y, w1.x, w1.y};
            #pragma unroll
            for (int r = 0; r < 4; r++)
                #pragma unroll
                for (int cp = 0; cp < 4; cp++)
                    acc[r][cp] = ffma2(ad[r], wp[cp], acc[r][cp]);
        }
        float* dst = (half == 0) ? g_S : g_P;
        #pragma unroll
        for (int r = 0; r < 4; r++) {
            int n = n0 + r0 + r;
            ulonglong2 q0, q1;
            q0.x = acc[r][0]; q0.y = acc[r][1];
            q1.x = acc[r][2]; q1.y = acc[r][3];
            *(ulonglong2*)&dst[n * C_DIM + c0]     = q0;
            *(ulonglong2*)&dst[n * C_DIM + c0 + 4] = q1;
        }
    }
}

// ---------------- K2: HMMA split-bf16 GEMM + gather epilogue ----------------
__global__ __launch_bounds__(128, 2) void k2_hmma(
        const float* __restrict__ nbr, const int* __restrict__ idx) {
    extern __shared__ __align__(1024) unsigned char SB[];
    const uint32_t sbase = smem_u32(SB);
    const int tid = threadIdx.x, wid = tid >> 5, lane = tid & 31;

    // stage W hi/lo (128 c-rows x 64 k bf16, SW128 rows of 128B)
    for (int i = tid; i < 128 * 8; i += 128) {
        int c = i >> 3, u = i & 7;
        uint32_t sw = SWZ((uint32_t)(c * 128 + u * 16));
        *(uint4*)(SB + SM_B_HI + sw) = *(const uint4*)&g_Wh[c * 64 + u * 8];
        *(uint4*)(SB + SM_B_LO + sw) = *(const uint4*)&g_Wl[c * 64 + u * 8];
    }
    __syncthreads();

    const int g    = lane >> 2, cq = lane & 3;
    const int sel  = lane >> 3;
    const int rsel = ((sel & 1) << 3) | (lane & 7);   // A: row within 16
    const int ksel = (sel >> 1) << 4;                 // A: k byte offset 0/16
    const int nsel = ((sel >> 1) << 3) | (lane & 7);  // B: n row within 16
    const int kselB = (sel & 1) << 4;                 // B: k byte offset 0/16
    unsigned char* aHi = SB + SM_A_HI + (wid << 12);
    unsigned char* aLo = SB + SM_A_LO + (wid << 12);
    const uint32_t aBaseHi = sbase + SM_A_HI + (wid << 12);
    const uint32_t aBaseLo = sbase + SM_A_LO + (wid << 12);
    const uint32_t eBase   = sbase + SM_E    + (wid << 13);
    unsigned char* ePtr    = SB + SM_E + (wid << 13);

    for (int wt = blockIdx.x * 4 + wid; wt < NWTILES; wt += gridDim.x * 4) {
        const int p0 = wt * 32;

        // load + split A slice (32 rows x 64 f32 -> bf16 hi/lo, SW128)
        #pragma unroll
        for (int pass = 0; pass < 4; ++pass) {
            int r  = pass * 8 + g;
            int c0 = cq * 16;
            #pragma unroll
            for (int q = 0; q < 4; ++q) {
                float4 v = __ldcs((const float4*)&nbr[(size_t)(p0 + r) * 64 + c0 + q * 4]);
                __nv_bfloat162 h0, h1, l0, l1;
                h0.x = __float2bfloat16(v.x); h0.y = __float2bfloat16(v.y);
                h1.x = __float2bfloat16(v.z); h1.y = __float2bfloat16(v.w);
                l0.x = __float2bfloat16(v.x - __bfloat162float(h0.x));
                l0.y = __float2bfloat16(v.y - __bfloat162float(h0.y));
                l1.x = __float2bfloat16(v.z - __bfloat162float(h1.x));
                l1.y = __float2bfloat16(v.w - __bfloat162float(h1.y));
                uint32_t sw = SWZ((uint32_t)(r * 128 + (c0 + q * 4) * 2));
                uint2 sh, sl;
                sh.x = *(uint32_t*)&h0; sh.y = *(uint32_t*)&h1;
                sl.x = *(uint32_t*)&l0; sl.y = *(uint32_t*)&l1;
                *(uint2*)(aHi + sw) = sh;
                *(uint2*)(aLo + sw) = sl;
            }
        }
        __syncwarp();

        #pragma unroll
        for (int h = 0; h < 2; ++h) {
            float acc[2][8][4];
            #pragma unroll
            for (int mf = 0; mf < 2; ++mf)
                #pragma unroll
                for (int nf = 0; nf < 8; ++nf)
                    #pragma unroll
                    for (int e = 0; e < 4; ++e) acc[mf][nf][e] = 0.f;

            #pragma unroll
            for (int ks = 0; ks < 4; ++ks) {
                uint32_t Ah[2][4], Al[2][4];
                #pragma unroll
                for (int mf = 0; mf < 2; ++mf) {
                    uint32_t byteA = (uint32_t)((mf * 16 + rsel) * 128 + ks * 32 + ksel);
                    ldsm4(Ah[mf], aBaseHi + SWZ(byteA));
                    ldsm4(Al[mf], aBaseLo + SWZ(byteA));
                }
                #pragma unroll
                for (int q = 0; q < 4; ++q) {
                    uint32_t byteB = (uint32_t)((h * 64 + q * 16 + nsel) * 128 + ks * 32 + kselB);
                    uint32_t Bh[4], Bl[4];
                    ldsm4(Bh, sbase + SM_B_HI + SWZ(byteB));
                    ldsm4(Bl, sbase + SM_B_LO + SWZ(byteB));
                    #pragma unroll
                    for (int mf = 0; mf < 2; ++mf) {
                        mma_bf16(acc[mf][q*2],   Ah[mf], Bh);
                        mma_bf16(acc[mf][q*2],   Al[mf], Bh);
                        mma_bf16(acc[mf][q*2],   Ah[mf], Bl);
                        mma_bf16(acc[mf][q*2+1], Ah[mf], Bh + 2);
                        mma_bf16(acc[mf][q*2+1], Al[mf], Bh + 2);
                        mma_bf16(acc[mf][q*2+1], Ah[mf], Bl + 2);
                    }
                }
            }

            // stage acc -> swizzled smem E (32 x 64 f32)
            #pragma unroll
            for (int mf = 0; mf < 2; ++mf)
                #pragma unroll
                for (int nf = 0; nf < 8; ++nf)
                    #pragma unroll
                    for (int rr = 0; rr < 2; ++rr) {
                        int r = mf * 16 + rr * 8 + g;
                        int c = nf * 8 + cq * 2;
                        uint32_t unit = ((uint32_t)r << 4) + ((uint32_t)(c >> 2) ^ (uint32_t)(r & 15));
                        uint32_t addr = eBase + (unit << 4) + ((uint32_t)(c & 3) << 2);
                        asm volatile("st.shared.v2.f32 [%0], {%1, %2};" ::
                            "r"(addr), "f"(acc[mf][nf][rr*2]), "f"(acc[mf][nf][rr*2+1]));
                    }
            __syncwarp();

            // gather S + P[idx], add E, store fp16 Z
            #pragma unroll
            for (int pass = 0; pass < 4; ++pass) {
                int r = pass * 8 + g;
                int p = p0 + r;
                int n = p / 12;
                int j = __ldg(&idx[p]);
                int cpart = cq * 16;
                float z[16];
                #pragma unroll
                for (int u = 0; u < 4; ++u) {
                    uint32_t unit = ((uint32_t)r << 4) +
                                    ((uint32_t)((cpart >> 2) + u) ^ (uint32_t)(r & 15));
                    float ex, ey, ez, ew;
                    asm volatile("ld.shared.v4.f32 {%0,%1,%2,%3}, [%4];"
                        : "=f"(ex), "=f"(ey), "=f"(ez), "=f"(ew) : "r"(eBase + (unit << 4)));
                    float4 s  = *(const float4*)&g_S[(size_t)n * C_DIM + h * 64 + cpart + u * 4];
                    float4 pv = *(const float4*)&g_P[(size_t)j * C_DIM + h * 64 + cpart + u * 4];
                    z[u*4+0] = ex + s.x + pv.x;
                    z[u*4+1] = ey + s.y + pv.y;
                    z[u*4+2] = ez + s.z + pv.z;
                    z[u*4+3] = ew + s.w + pv.w;
                }
                uint4 st0, st1;
                {
                    __half2 a0 = __floats2half2_rn(z[0],  z[1]);
                    __half2 a1 = __floats2half2_rn(z[2],  z[3]);
                    __half2 a2 = __floats2half2_rn(z[4],  z[5]);
                    __half2 a3 = __floats2half2_rn(z[6],  z[7]);
                    __half2 a4 = __floats2half2_rn(z[8],  z[9]);
                    __half2 a5 = __floats2half2_rn(z[10], z[11]);
                    __half2 a6 = __floats2half2_rn(z[12], z[13]);
                    __half2 a7 = __floats2half2_rn(z[14], z[15]);
                    st0.x = *(uint32_t*)&a0; st0.y = *(uint32_t*)&a1;
                    st0.z = *(uint32_t*)&a2; st0.w = *(uint32_t*)&a3;
                    st1.x = *(uint32_t*)&a4; st1.y = *(uint32_t*)&a5;
                    st1.z = *(uint32_t*)&a6; st1.w = *(uint32_t*)&a7;
                }
                __stcs((uint4*)&g_Zh[(size_t)p * C_DIM + h * 64 + cpart],     st0);
                __stcs((uint4*)&g_Zh[(size_t)p * C_DIM + h * 64 + cpart + 8], st1);
            }
            __syncwarp();
        }
    }
    (void)ePtr;
}

// ---------------- K2b: BN1 stats over fp16 Z ----------------
__global__ __launch_bounds__(256) void k2b_stats() {
    __shared__ float sS[128], sQ[128];
    const int tid = threadIdx.x;
    if (tid < 128) { sS[tid] = 0.f; sQ[tid] = 0.f; }
    __syncthreads();
    const int c  = tid & 63;
    const int rl = tid >> 6;
    float s0 = 0.f, q0 = 0.f, s1 = 0.f, q1 = 0.f;
    for (int row = blockIdx.x * 4 + rl; row < P_ROWS; row += gridDim.x * 4) {
        __half2 h = __ldcs((const __half2*)&g_Zh[(size_t)row * C_DIM + c * 2]);
        float2 f = __half22float2(h);
        s0 += f.x; q0 = fmaf(f.x, f.x, q0);
        s1 += f.y; q1 = fmaf(f.y, f.y, q1);
    }
    atomicAdd(&sS[2*c],   s0); atomicAdd(&sQ[2*c],   q0);
    atomicAdd(&sS[2*c+1], s1); atomicAdd(&sQ[2*c+1], q1);
    __syncthreads();
    if (tid < 128) {
        atomicAdd(&g_stats1[tid],       sS[tid]);
        atomicAdd(&g_stats1[128 + tid], sQ[tid]);
    }
}

// ---------------- K3 ----------------
__global__ void k3_aff1(const float* __restrict__ gamma1,
                        const float* __restrict__ beta1) {
    int c = threadIdx.x;
    float inv  = 1.f / (float)P_ROWS;
    float mean = g_stats1[c] * inv;
    float var  = g_stats1[128 + c] * inv - mean * mean;
    float sc   = gamma1[c] * rsqrtf(var + BN_EPS);
    g_aff1[c]       = sc;
    g_aff1[128 + c] = beta1[c] - mean * sc;
}

// ---------------- K4 ----------------
__global__ __launch_bounds__(256) void k4_reduce(const float* __restrict__ bw) {
    __shared__ float sSum[64], sSq[64];
    const int tid = threadIdx.x;
    if (tid < 64) { sSum[tid] = 0.f; sSq[tid] = 0.f; }
    __syncthreads();
    const int f2 = (tid & 31) * 2;
    const int al = tid >> 5;
    const float sc1a = g_aff1[f2],        sh1a = g_aff1[128 + f2];
    const float sc1b = g_aff1[f2 + 1],    sh1b = g_aff1[128 + f2 + 1];
    const float sc2a = g_aff1[64 + f2],   sh2a = g_aff1[192 + f2];
    const float sc2b = g_aff1[64 + f2+1], sh2b = g_aff1[192 + f2 + 1];
    float lsa = 0.f, lqa = 0.f, lsb = 0.f, lqb = 0.f;
    for (int n = blockIdx.x * 8 + al; n < N_ATOMS; n += gridDim.x * 8) {
        float acca = 0.f, accb = 0.f;
        #pragma unroll
        for (int m = 0; m < 12; m++) {
            size_t base = (size_t)(n * 12 + m) * C_DIM;
            float2 v1 = __half22float2(*(const __half2*)&g_Zh[base + f2]);
            float2 v2 = __half22float2(*(const __half2*)&g_Zh[base + 64 + f2]);
            float z1a = fmaf(v1.x, sc1a, sh1a);
            float z1b = fmaf(v1.y, sc1b, sh1b);
            float z2a = fmaf(v2.x, sc2a, sh2a);
            float z2b = fmaf(v2.y, sc2b, sh2b);
            float w  = __ldg(&bw[n * 12 + m]);
            float w2 = w * w;
            acca = fmaf(w2 * sigmoid_fast(z1a), softplus_fast(z2a), acca);
            accb = fmaf(w2 * sigmoid_fast(z1b), softplus_fast(z2b), accb);
        }
        *(float2*)&g_NS[n * 64 + f2] = make_float2(acca, accb);
        lsa += acca; lqa = fmaf(acca, acca, lqa);
        lsb += accb; lqb = fmaf(accb, accb, lqb);
    }
    atomicAdd(&sSum[f2],     lsa);
    atomicAdd(&sSum[f2 + 1], lsb);
    atomicAdd(&sSq[f2],      lqa);
    atomicAdd(&sSq[f2 + 1],  lqb);
    __syncthreads();
    if (tid < 64) {
        atomicAdd(&g_stats2[tid],      sSum[tid]);
        atomicAdd(&g_stats2[64 + tid], sSq[tid]);
    }
}

// ---------------- K5 ----------------
__global__ void k5_aff2(const float* __restrict__ gamma2,
                        const float* __restrict__ beta2) {
    int f = threadIdx.x;
    float inv  = 1.f / (float)N_ATOMS;
    float mean = g_stats2[f] * inv;
    float var  = g_stats2[64 + f] * inv - mean * mean;
    float sc   = gamma2[f] * rsqrtf(var + BN_EPS);
    g_aff2[f]      = sc;
    g_aff2[64 + f] = beta2[f] - mean * sc;
}

// ---------------- K6 ----------------
__global__ void k6_out(const float* __restrict__ atom, float* __restrict__ out) {
    int i = blockIdx.x * blockDim.x + threadIdx.x;
    if (i < N_ATOMS * F_DIM) {
        int f = i & 63;
        float x = atom[i] + fmaf(g_NS[i], g_aff2[f], g_aff2[64 + f]);
        out[i] = softplus_fast(x);
    }
}

// ---------------- launch ----------------
extern "C" void kernel_launch(void* const* d_in, const int* in_sizes, int n_in,
                              void* d_out, int out_size) {
    const float* atom   = (const float*)d_in[0];
    const float* nbr    = (const float*)d_in[1];
    const float* bw     = (const float*)d_in[2];
    const int*   idx    = (const int*)  d_in[3];
    const float* W      = (const float*)d_in[4];
    const float* b      = (const float*)d_in[5];
    const float* gamma1 = (const float*)d_in[6];
    const float* beta1  = (const float*)d_in[7];
    const float* gamma2 = (const float*)d_in[8];
    const float* beta2  = (const float*)d_in[9];
    float* out = (float*)d_out;

    cudaFuncSetAttribute(k2_hmma, cudaFuncAttributeMaxDynamicSharedMemorySize, SM_TOT);

    k0_zero<<<2, 256>>>(W);
    k1_selfnbr<<<N_ATOMS / 32, 128>>>(atom, W, b);
    knop<<<1, 32>>>();
    k2_hmma<<<296, 128, SM_TOT>>>(nbr, idx);
    k2b_stats<<<592, 256>>>();
    k3_aff1<<<1, 128>>>(gamma1, beta1);
    k4_reduce<<<592, 256>>>(bw);
    k5_aff2<<<1, 64>>>(gamma2, beta2);
    k6_out<<<(N_ATOMS * F_DIM + 255) / 256, 256>>>(atom, out);
}

// round 10
// speedup vs baseline: 1.2211x; 1.2211x over previous
#include <cuda_runtime.h>
#include <cuda_fp16.h>
#include <cuda_bf16.h>
#include <stdint.h>
#include <math.h>

#define N_ATOMS 100000
#define M_NBR   12
#define F_DIM   64
#define C_DIM   128
#define KW      192
#define P_ROWS  (N_ATOMS * M_NBR)  // 1200000
#define BN_EPS  1e-5f
#define NWTILES (P_ROWS / 32)      // 37500 warp-tiles of 32 rows

typedef unsigned long long u64;

// ---------------- scratch ----------------
__device__ __align__(256) float  g_S [N_ATOMS * C_DIM];
__device__ __align__(256) float  g_P [N_ATOMS * C_DIM];
__device__ __align__(256) __half g_Zh[(size_t)P_ROWS * C_DIM];
__device__ __align__(256) float  g_NS[N_ATOMS * F_DIM];
__device__ __align__(256) __nv_bfloat16 g_Wh[C_DIM * 64];   // W_edge hi (bf16)
__device__ __align__(256) __nv_bfloat16 g_Wl[C_DIM * 64];   // W_edge lo (bf16)
__device__ float g_stats1[2 * C_DIM];
__device__ float g_stats2[2 * F_DIM];
__device__ float g_aff1 [2 * C_DIM];
__device__ float g_aff2 [2 * F_DIM];

// ---------------- helpers ----------------
__device__ __forceinline__ u64 pack2(float lo, float hi) {
    u64 r; asm("mov.b64 %0, {%1, %2};" : "=l"(r) : "r"(__float_as_uint(lo)), "r"(__float_as_uint(hi))); return r;
}
__device__ __forceinline__ u64 dup2(float a) {
    u64 r; unsigned int u = __float_as_uint(a);
    asm("mov.b64 %0, {%1, %1};" : "=l"(r) : "r"(u)); return r;
}
__device__ __forceinline__ u64 ffma2(u64 a, u64 b, u64 c) {
    u64 d; asm("fma.rn.f32x2 %0, %1, %2, %3;" : "=l"(d) : "l"(a), "l"(b), "l"(c)); return d;
}
__device__ __forceinline__ float tanh_fast(float x) {
    float y; asm("tanh.approx.f32 %0, %1;" : "=f"(y) : "f"(x)); return y;
}
__device__ __forceinline__ float sigmoid_fast(float x) {
    return fmaf(0.5f, tanh_fast(0.5f * x), 0.5f);
}
__device__ __forceinline__ float softplus_fast(float x) {
    return fmaxf(x, 0.f) + __logf(1.f + __expf(-fabsf(x)));
}
__device__ __forceinline__ uint32_t smem_u32(const void* p) {
    uint32_t a;
    asm("{ .reg .u64 t; cvta.to.shared.u64 t, %1; cvt.u32.u64 %0, t; }" : "=r"(a) : "l"(p));
    return a;
}
#define SWZ(b) ((b) ^ (((b) >> 3) & 0x70))

__device__ __forceinline__ void ldsm4(uint32_t* r, uint32_t addr) {
    asm volatile("ldmatrix.sync.aligned.m8n8.x4.shared.b16 {%0,%1,%2,%3}, [%4];"
        : "=r"(r[0]), "=r"(r[1]), "=r"(r[2]), "=r"(r[3]) : "r"(addr));
}
__device__ __forceinline__ void mma_bf16(float* d, const uint32_t* a, const uint32_t* b) {
    asm volatile("mma.sync.aligned.m16n8k16.row.col.f32.bf16.bf16.f32 "
        "{%0,%1,%2,%3}, {%4,%5,%6,%7}, {%8,%9}, {%0,%1,%2,%3};"
        : "+f"(d[0]), "+f"(d[1]), "+f"(d[2]), "+f"(d[3])
        : "r"(a[0]), "r"(a[1]), "r"(a[2]), "r"(a[3]), "r"(b[0]), "r"(b[1]));
}

// k2 smem layout (dynamic, 80KB)
#define SM_B_HI 0
#define SM_B_LO 16384
#define SM_A_HI 32768       // + wid*4096 (32 rows x 128B)
#define SM_E    49152       // + wid*8192 (32 x 64 f32)
#define SM_TOT  81920

// ---------------- K0: zero stats + split W_edge to bf16 hi/lo --------------
__global__ void k0_zero(const float* __restrict__ W) {
    int t = blockIdx.x * blockDim.x + threadIdx.x;
    if (t < 2 * C_DIM) g_stats1[t] = 0.f;
    if (t < 2 * F_DIM) g_stats2[t] = 0.f;
    for (int i = t; i < C_DIM * 64; i += gridDim.x * blockDim.x) {
        int c = i >> 6, k = i & 63;
        float x = W[c * KW + 128 + k];
        __nv_bfloat16 hi = __float2bfloat16(x);
        __nv_bfloat16 lo = __float2bfloat16(x - __bfloat162float(hi));
        g_Wh[i] = hi; g_Wl[i] = lo;
    }
}

__global__ void knop() {}

// ---------------- K1: S, P precompute (FFMA2 path) ----------------
__global__ __launch_bounds__(128, 4) void k1_selfnbr(
        const float* __restrict__ atom, const float* __restrict__ W,
        const float* __restrict__ b) {
    __shared__ __align__(16) float sW[64 * 128];
    __shared__ __align__(16) float sA[64 * 36];
    const int tid = threadIdx.x;
    const int n0  = blockIdx.x * 32;
    for (int i = tid; i < 32 * 64; i += 128) {
        int r = i >> 6, k = i & 63;
        sA[k * 36 + r] = atom[(n0 + r) * 64 + k];
    }
    const int rg = tid >> 4, cg = tid & 15;
    const int r0 = rg * 4,  c0 = cg * 8;
    for (int half = 0; half < 2; ++half) {
        __syncthreads();
        for (int i = tid; i < 64 * 128; i += 128) {
            int c = i >> 6, k = i & 63;
            sW[k * 128 + c] = W[c * KW + half * 64 + k];
        }
        __syncthreads();
        u64 acc[4][4];
        #pragma unroll
        for (int r = 0; r < 4; r++)
            #pragma unroll
            for (int cp = 0; cp < 4; cp++)
                acc[r][cp] = (half == 0) ? pack2(b[c0 + 2*cp], b[c0 + 2*cp + 1]) : 0ULL;
        #pragma unroll 8
        for (int k = 0; k < 64; ++k) {
            float4 av = *(const float4*)&sA[k * 36 + r0];
            ulonglong2 w0 = *(const ulonglong2*)&sW[k * 128 + c0];
            ulonglong2 w1 = *(const ulonglong2*)&sW[k * 128 + c0 + 4];
            u64 ad[4] = {dup2(av.x), dup2(av.y), dup2(av.z), dup2(av.w)};
            u64 wp[4] = {w0.x, w0.y, w1.x, w1.y};
            #pragma unroll
            for (int r = 0; r < 4; r++)
                #pragma unroll
                for (int cp = 0; cp < 4; cp++)
                    acc[r][cp] = ffma2(ad[r], wp[cp], acc[r][cp]);
        }
        float* dst = (half == 0) ? g_S : g_P;
        #pragma unroll
        for (int r = 0; r < 4; r++) {
            int n = n0 + r0 + r;
            ulonglong2 q0, q1;
            q0.x = acc[r][0]; q0.y = acc[r][1];
            q1.x = acc[r][2]; q1.y = acc[r][3];
            *(ulonglong2*)&dst[n * C_DIM + c0]     = q0;
            *(ulonglong2*)&dst[n * C_DIM + c0 + 4] = q1;
        }
    }
}

// ---------------- K2: HMMA GEMM + gather epilogue + fused BN1 stats --------
__global__ __launch_bounds__(128, 2) void k2_hmma(
        const float* __restrict__ nbr, const int* __restrict__ idx) {
    extern __shared__ __align__(1024) unsigned char SB[];
    const uint32_t sbase = smem_u32(SB);
    const int tid = threadIdx.x, wid = tid >> 5, lane = tid & 31;

    // stage W hi/lo (128 c-rows x 64 k bf16, SW128 rows of 128B)
    for (int i = tid; i < 128 * 8; i += 128) {
        int c = i >> 3, u = i & 7;
        uint32_t sw = SWZ((uint32_t)(c * 128 + u * 16));
        *(uint4*)(SB + SM_B_HI + sw) = *(const uint4*)&g_Wh[c * 64 + u * 8];
        *(uint4*)(SB + SM_B_LO + sw) = *(const uint4*)&g_Wl[c * 64 + u * 8];
    }
    __syncthreads();

    const int g    = lane >> 2, cq = lane & 3;
    const int sel  = lane >> 3;
    const int rsel = ((sel & 1) << 3) | (lane & 7);   // A: row within 16
    const int ksel = (sel >> 1) << 4;                 // A: k byte offset 0/16
    const int nsel = ((sel >> 1) << 3) | (lane & 7);  // B: n row within 16
    const int kselB = (sel & 1) << 4;                 // B: k byte offset 0/16
    unsigned char* aHi = SB + SM_A_HI + (wid << 12);
    const uint32_t aBaseHi = sbase + SM_A_HI + (wid << 12);
    const uint32_t eBase   = sbase + SM_E    + (wid << 13);

    float lsum[2][16], lsq[2][16];
    #pragma unroll
    for (int h = 0; h < 2; ++h)
        #pragma unroll
        for (int i = 0; i < 16; ++i) { lsum[h][i] = 0.f; lsq[h][i] = 0.f; }

    for (int wt = blockIdx.x * 4 + wid; wt < NWTILES; wt += gridDim.x * 4) {
        const int p0 = wt * 32;

        // load A slice (32 rows x 64 f32 -> bf16 hi only, SW128)
        #pragma unroll
        for (int pass = 0; pass < 4; ++pass) {
            int r  = pass * 8 + g;
            int c0 = cq * 16;
            #pragma unroll
            for (int q = 0; q < 4; ++q) {
                float4 v = __ldcs((const float4*)&nbr[(size_t)(p0 + r) * 64 + c0 + q * 4]);
                __nv_bfloat162 h0, h1;
                h0.x = __float2bfloat16(v.x); h0.y = __float2bfloat16(v.y);
                h1.x = __float2bfloat16(v.z); h1.y = __float2bfloat16(v.w);
                uint32_t sw = SWZ((uint32_t)(r * 128 + (c0 + q * 4) * 2));
                uint2 sh;
                sh.x = *(uint32_t*)&h0; sh.y = *(uint32_t*)&h1;
                *(uint2*)(aHi + sw) = sh;
            }
        }
        __syncwarp();

        // preload all A fragments for this tile (8 ldsm4)
        uint32_t Af[4][2][4];
        #pragma unroll
        for (int ks = 0; ks < 4; ++ks)
            #pragma unroll
            for (int mf = 0; mf < 2; ++mf) {
                uint32_t byteA = (uint32_t)((mf * 16 + rsel) * 128 + ks * 32 + ksel);
                ldsm4(Af[ks][mf], aBaseHi + SWZ(byteA));
            }

        #pragma unroll
        for (int h = 0; h < 2; ++h) {
            float acc[2][8][4];
            #pragma unroll
            for (int mf = 0; mf < 2; ++mf)
                #pragma unroll
                for (int nf = 0; nf < 8; ++nf)
                    #pragma unroll
                    for (int e = 0; e < 4; ++e) acc[mf][nf][e] = 0.f;

            #pragma unroll
            for (int ks = 0; ks < 4; ++ks) {
                #pragma unroll
                for (int q = 0; q < 4; ++q) {
                    uint32_t byteB = (uint32_t)((h * 64 + q * 16 + nsel) * 128 + ks * 32 + kselB);
                    uint32_t Bh[4], Bl[4];
                    ldsm4(Bh, sbase + SM_B_HI + SWZ(byteB));
                    ldsm4(Bl, sbase + SM_B_LO + SWZ(byteB));
                    #pragma unroll
                    for (int mf = 0; mf < 2; ++mf) {
                        mma_bf16(acc[mf][q*2],   Af[ks][mf], Bh);
                        mma_bf16(acc[mf][q*2],   Af[ks][mf], Bl);
                        mma_bf16(acc[mf][q*2+1], Af[ks][mf], Bh + 2);
                        mma_bf16(acc[mf][q*2+1], Af[ks][mf], Bl + 2);
                    }
                }
            }

            // stage acc -> swizzled smem E (32 x 64 f32)
            #pragma unroll
            for (int mf = 0; mf < 2; ++mf)
                #pragma unroll
                for (int nf = 0; nf < 8; ++nf)
                    #pragma unroll
                    for (int rr = 0; rr < 2; ++rr) {
                        int r = mf * 16 + rr * 8 + g;
                        int c = nf * 8 + cq * 2;
                        uint32_t unit = ((uint32_t)r << 4) + ((uint32_t)(c >> 2) ^ (uint32_t)(r & 15));
                        uint32_t addr = eBase + (unit << 4) + ((uint32_t)(c & 3) << 2);
                        asm volatile("st.shared.v2.f32 [%0], {%1, %2};" ::
                            "r"(addr), "f"(acc[mf][nf][rr*2]), "f"(acc[mf][nf][rr*2+1]));
                    }
            __syncwarp();

            // gather S + P[idx], add E, accumulate stats, store fp16 Z
            #pragma unroll
            for (int pass = 0; pass < 4; ++pass) {
                int r = pass * 8 + g;
                int p = p0 + r;
                int n = p / 12;
                int j = __ldg(&idx[p]);
                int cpart = cq * 16;
                float z[16];
                #pragma unroll
                for (int u = 0; u < 4; ++u) {
                    uint32_t unit = ((uint32_t)r << 4) +
                                    ((uint32_t)((cpart >> 2) + u) ^ (uint32_t)(r & 15));
                    float ex, ey, ez, ew;
                    asm volatile("ld.shared.v4.f32 {%0,%1,%2,%3}, [%4];"
                        : "=f"(ex), "=f"(ey), "=f"(ez), "=f"(ew) : "r"(eBase + (unit << 4)));
                    float4 s  = *(const float4*)&g_S[(size_t)n * C_DIM + h * 64 + cpart + u * 4];
                    float4 pv = *(const float4*)&g_P[(size_t)j * C_DIM + h * 64 + cpart + u * 4];
                    z[u*4+0] = ex + s.x + pv.x;
                    z[u*4+1] = ey + s.y + pv.y;
                    z[u*4+2] = ez + s.z + pv.z;
                    z[u*4+3] = ew + s.w + pv.w;
                }
                #pragma unroll
                for (int e = 0; e < 16; ++e) {
                    lsum[h][e] += z[e];
                    lsq[h][e]  = fmaf(z[e], z[e], lsq[h][e]);
                }
                uint4 st0, st1;
                {
                    __half2 a0 = __floats2half2_rn(z[0],  z[1]);
                    __half2 a1 = __floats2half2_rn(z[2],  z[3]);
                    __half2 a2 = __floats2half2_rn(z[4],  z[5]);
                    __half2 a3 = __floats2half2_rn(z[6],  z[7]);
                    __half2 a4 = __floats2half2_rn(z[8],  z[9]);
                    __half2 a5 = __floats2half2_rn(z[10], z[11]);
                    __half2 a6 = __floats2half2_rn(z[12], z[13]);
                    __half2 a7 = __floats2half2_rn(z[14], z[15]);
                    st0.x = *(uint32_t*)&a0; st0.y = *(uint32_t*)&a1;
                    st0.z = *(uint32_t*)&a2; st0.w = *(uint32_t*)&a3;
                    st1.x = *(uint32_t*)&a4; st1.y = *(uint32_t*)&a5;
                    st1.z = *(uint32_t*)&a6; st1.w = *(uint32_t*)&a7;
                }
                __stcs((uint4*)&g_Zh[(size_t)p * C_DIM + h * 64 + cpart],     st0);
                __stcs((uint4*)&g_Zh[(size_t)p * C_DIM + h * 64 + cpart + 8], st1);
            }
            __syncwarp();
        }
    }

    // ---- CTA-level stats reduction (reuses B_HI smem region) ----
    __syncthreads();
    float* st = (float*)SB;       // 512 floats: [sum 256 | unused][sq]
    for (int i = tid; i < 512; i += 128) st[i] = 0.f;
    __syncthreads();
    #pragma unroll
    for (int h = 0; h < 2; ++h)
        #pragma unroll
        for (int e = 0; e < 16; ++e) {
            int ch = h * 64 + cq * 16 + e;
            atomicAdd(&st[ch],       lsum[h][e]);
            atomicAdd(&st[256 + ch], lsq[h][e]);
        }
    __syncthreads();
    if (tid < 128) {
        atomicAdd(&g_stats1[tid],       st[tid]);
        atomicAdd(&g_stats1[128 + tid], st[256 + tid]);
    }
}

// ---------------- K3 ----------------
__global__ void k3_aff1(const float* __restrict__ gamma1,
                        const float* __restrict__ beta1) {
    int c = threadIdx.x;
    float inv  = 1.f / (float)P_ROWS;
    float mean = g_stats1[c] * inv;
    float var  = g_stats1[128 + c] * inv - mean * mean;
    float sc   = gamma1[c] * rsqrtf(var + BN_EPS);
    g_aff1[c]       = sc;
    g_aff1[128 + c] = beta1[c] - mean * sc;
}

// ---------------- K4 ----------------
__global__ __launch_bounds__(256) void k4_reduce(const float* __restrict__ bw) {
    __shared__ float sSum[64], sSq[64];
    const int tid = threadIdx.x;
    if (tid < 64) { sSum[tid] = 0.f; sSq[tid] = 0.f; }
    __syncthreads();
    const int f2 = (tid & 31) * 2;
    const int al = tid >> 5;
    const float sc1a = g_aff1[f2],        sh1a = g_aff1[128 + f2];
    const float sc1b = g_aff1[f2 + 1],    sh1b = g_aff1[128 + f2 + 1];
    const float sc2a = g_aff1[64 + f2],   sh2a = g_aff1[192 + f2];
    const float sc2b = g_aff1[64 + f2+1], sh2b = g_aff1[192 + f2 + 1];
    float lsa = 0.f, lqa = 0.f, lsb = 0.f, lqb = 0.f;
    for (int n = blockIdx.x * 8 + al; n < N_ATOMS; n += gridDim.x * 8) {
        float acca = 0.f, accb = 0.f;
        #pragma unroll
        for (int m = 0; m < 12; m++) {
            size_t base = (size_t)(n * 12 + m) * C_DIM;
            float2 v1 = __half22float2(*(const __half2*)&g_Zh[base + f2]);
            float2 v2 = __half22float2(*(const __half2*)&g_Zh[base + 64 + f2]);
            float z1a = fmaf(v1.x, sc1a, sh1a);
            float z1b = fmaf(v1.y, sc1b, sh1b);
            float z2a = fmaf(v2.x, sc2a, sh2a);
            float z2b = fmaf(v2.y, sc2b, sh2b);
            float w  = __ldg(&bw[n * 12 + m]);
            float w2 = w * w;
            acca = fmaf(w2 * sigmoid_fast(z1a), softplus_fast(z2a), acca);
            accb = fmaf(w2 * sigmoid_fast(z1b), softplus_fast(z2b), accb);
        }
        *(float2*)&g_NS[n * 64 + f2] = make_float2(acca, accb);
        lsa += acca; lqa = fmaf(acca, acca, lqa);
        lsb += accb; lqb = fmaf(accb, accb, lqb);
    }
    atomicAdd(&sSum[f2],     lsa);
    atomicAdd(&sSum[f2 + 1], lsb);
    atomicAdd(&sSq[f2],      lqa);
    atomicAdd(&sSq[f2 + 1],  lqb);
    __syncthreads();
    if (tid < 64) {
        atomicAdd(&g_stats2[tid],      sSum[tid]);
        atomicAdd(&g_stats2[64 + tid], sSq[tid]);
    }
}

// ---------------- K5 ----------------
__global__ void k5_aff2(const float* __restrict__ gamma2,
                        const float* __restrict__ beta2) {
    int f = threadIdx.x;
    float inv  = 1.f / (float)N_ATOMS;
    float mean = g_stats2[f] * inv;
    float var  = g_stats2[64 + f] * inv - mean * mean;
    float sc   = gamma2[f] * rsqrtf(var + BN_EPS);
    g_aff2[f]      = sc;
    g_aff2[64 + f] = beta2[f] - mean * sc;
}

// ---------------- K6 ----------------
__global__ void k6_out(const float* __restrict__ atom, float* __restrict__ out) {
    int i = blockIdx.x * blockDim.x + threadIdx.x;
    if (i < N_ATOMS * F_DIM) {
        int f = i & 63;
        float x = atom[i] + fmaf(g_NS[i], g_aff2[f], g_aff2[64 + f]);
        out[i] = softplus_fast(x);
    }
}

// ---------------- launch ----------------
extern "C" void kernel_launch(void* const* d_in, const int* in_sizes, int n_in,
                              void* d_out, int out_size) {
    const float* atom   = (const float*)d_in[0];
    const float* nbr    = (const float*)d_in[1];
    const float* bw     = (const float*)d_in[2];
    const int*   idx    = (const int*)  d_in[3];
    const float* W      = (const float*)d_in[4];
    const float* b      = (const float*)d_in[5];
    const float* gamma1 = (const float*)d_in[6];
    const float* beta1  = (const float*)d_in[7];
    const float* gamma2 = (const float*)d_in[8];
    const float* beta2  = (const float*)d_in[9];
    float* out = (float*)d_out;

    cudaFuncSetAttribute(k2_hmma, cudaFuncAttributeMaxDynamicSharedMemorySize, SM_TOT);

    k0_zero<<<2, 256>>>(W);
    k1_selfnbr<<<N_ATOMS / 32, 128>>>(atom, W, b);
    knop<<<1, 32>>>();
    k2_hmma<<<296, 128, SM_TOT>>>(nbr, idx);
    k3_aff1<<<1, 128>>>(gamma1, beta1);
    k4_reduce<<<592, 256>>>(bw);
    k5_aff2<<<1, 64>>>(gamma2, beta2);
    k6_out<<<(N_ATOMS * F_DIM + 255) / 256, 256>>>(atom, out);
}